// round 12
// baseline (speedup 1.0000x reference)
#include <cuda_runtime.h>

// SparseDenseMatMul: out[m,n] = sum_{i: rows[i]==m} vals[i] * A[cols[i], n]
// M = 100000, K = 100000, N = 64, NNZ = 1.6M
//
// Inputs (metadata order):
//   d_in[0] = vals (float, NNZ), d_in[1] = A (float, K*N),
//   d_in[2] = rows (int, NNZ),   d_in[3] = cols (int, NNZ)
// Output: float, M*N
//
// 2-kernel pipeline:
//   B: bin nnz into fixed-capacity per-row buckets (scalar ticket atomics),
//      4 nnz per thread. Counters start zero (module zero-init on first
//      call; phase C restores them to zero every call).
//   C: HALF-WARP per output row (16 lanes x float4 = 64 cols), two rows per
//      warp. Software-pipelined: next group's uniform bucket loads are
//      issued while the current group's 8 independent A-row gathers are in
//      flight, so the bucket->gather latency chain is overlapped.

#define N_COLS     64
#define M_ROWS     100000
#define BUCKET_CAP 64
#define OVF_CAP    8192

__device__ int  d_cnt[M_ROWS];                           // zero-initialized
__device__ int2 d_bucket[(size_t)M_ROWS * BUCKET_CAP];   // (col, val-bits)
__device__ int  d_ovf_cnt;                               // zero-initialized
__device__ int  d_ovf[OVF_CAP];

// ---------------- Phase B: bin nnz into per-row buckets ----------------
__device__ __forceinline__ void bin_one(int r, int c, float v, int i) {
    int pos = atomicAdd(&d_cnt[r], 1);
    if (pos < BUCKET_CAP) {
        d_bucket[(size_t)r * BUCKET_CAP + pos] = make_int2(c, __float_as_int(v));
    } else {
        int o = atomicAdd(&d_ovf_cnt, 1);
        if (o < OVF_CAP) d_ovf[o] = i;
    }
}

__global__ void __launch_bounds__(256)
phaseB_scatter(const float4* __restrict__ vals4,
               const int4*   __restrict__ rows4,
               const int4*   __restrict__ cols4,
               int nnz) {
    int t  = blockIdx.x * blockDim.x + threadIdx.x;
    int i0 = t * 4;
    if (i0 >= nnz) return;

    int4   r4 = rows4[t];
    int4   c4 = cols4[t];
    float4 v4 = vals4[t];

    bin_one(r4.x, c4.x, v4.x, i0);
    if (i0 + 1 < nnz) bin_one(r4.y, c4.y, v4.y, i0 + 1);
    if (i0 + 2 < nnz) bin_one(r4.z, c4.z, v4.z, i0 + 2);
    if (i0 + 3 < nnz) bin_one(r4.w, c4.w, v4.w, i0 + 3);
}

// ---------------- Phase C: half-warp-per-row, pipelined gather ----------
__global__ void __launch_bounds__(256)
phaseC_spmm(const float4* __restrict__ A4,
            float4*       __restrict__ out4,
            const float*  __restrict__ vals,
            const int*    __restrict__ rows,
            const int*    __restrict__ cols,
            int m) {
    int gtid = blockIdx.x * blockDim.x + threadIdx.x;
    int w    = gtid >> 5;             // warp id: handles rows 2w, 2w+1
    int lane = threadIdx.x & 31;
    int half = lane >> 4;             // which row of the pair
    int sub  = lane & 15;             // float4 slice within the row
    int r0   = w << 1;
    if (r0 >= m) return;
    int row  = r0 + half;

    // Both rows' counters with one uniform 8B load (r0 even -> aligned).
    int2 cnt2 = __ldg((const int2*)(d_cnt + r0));
    int c  = half ? cnt2.y : cnt2.x;
    if (row >= m) c = 0;              // m odd, phantom second row
    int cc = c < BUCKET_CAP ? c : BUCKET_CAP;

    // Bucket for this half's row (512B-aligned). When row==m (phantom) the
    // pointer is clamped to row 0; cc==0 so nothing is consumed.
    const int4* bk4 =
        (const int4*)(d_bucket + (size_t)(row < m ? row : 0) * BUCKET_CAP);

    float4 acc = make_float4(0.f, 0.f, 0.f, 0.f);

    int k = 0;
    if (cc >= 8) {
        // Prologue: load group 0's 4 uniform int4 (8 entries).
        int4 q0 = __ldg(&bk4[0]);
        int4 q1 = __ldg(&bk4[1]);
        int4 q2 = __ldg(&bk4[2]);
        int4 q3 = __ldg(&bk4[3]);
        for (; k + 8 <= cc; k += 8) {
            int4 p0 = q0, p1 = q1, p2 = q2, p3 = q3;
            // Prefetch next group while this group's gathers are in flight.
            // Clamp to stay inside this row's 64-entry bucket (indices<=31).
            int h = (k >> 1) + 4;
            if (h > 28) h = 28;
            q0 = __ldg(&bk4[h + 0]);
            q1 = __ldg(&bk4[h + 1]);
            q2 = __ldg(&bk4[h + 2]);
            q3 = __ldg(&bk4[h + 3]);
            float4 a0 = __ldg(&A4[(size_t)p0.x * 16 + sub]);
            float4 a1 = __ldg(&A4[(size_t)p0.z * 16 + sub]);
            float4 a2 = __ldg(&A4[(size_t)p1.x * 16 + sub]);
            float4 a3 = __ldg(&A4[(size_t)p1.z * 16 + sub]);
            float4 a4 = __ldg(&A4[(size_t)p2.x * 16 + sub]);
            float4 a5 = __ldg(&A4[(size_t)p2.z * 16 + sub]);
            float4 a6 = __ldg(&A4[(size_t)p3.x * 16 + sub]);
            float4 a7 = __ldg(&A4[(size_t)p3.z * 16 + sub]);
            float v0 = __int_as_float(p0.y), v1 = __int_as_float(p0.w);
            float v2 = __int_as_float(p1.y), v3 = __int_as_float(p1.w);
            float v4 = __int_as_float(p2.y), v5 = __int_as_float(p2.w);
            float v6 = __int_as_float(p3.y), v7 = __int_as_float(p3.w);
            acc.x = fmaf(v0, a0.x, acc.x); acc.y = fmaf(v0, a0.y, acc.y);
            acc.z = fmaf(v0, a0.z, acc.z); acc.w = fmaf(v0, a0.w, acc.w);
            acc.x = fmaf(v1, a1.x, acc.x); acc.y = fmaf(v1, a1.y, acc.y);
            acc.z = fmaf(v1, a1.z, acc.z); acc.w = fmaf(v1, a1.w, acc.w);
            acc.x = fmaf(v2, a2.x, acc.x); acc.y = fmaf(v2, a2.y, acc.y);
            acc.z = fmaf(v2, a2.z, acc.z); acc.w = fmaf(v2, a2.w, acc.w);
            acc.x = fmaf(v3, a3.x, acc.x); acc.y = fmaf(v3, a3.y, acc.y);
            acc.z = fmaf(v3, a3.z, acc.z); acc.w = fmaf(v3, a3.w, acc.w);
            acc.x = fmaf(v4, a4.x, acc.x); acc.y = fmaf(v4, a4.y, acc.y);
            acc.z = fmaf(v4, a4.z, acc.z); acc.w = fmaf(v4, a4.w, acc.w);
            acc.x = fmaf(v5, a5.x, acc.x); acc.y = fmaf(v5, a5.y, acc.y);
            acc.z = fmaf(v5, a5.z, acc.z); acc.w = fmaf(v5, a5.w, acc.w);
            acc.x = fmaf(v6, a6.x, acc.x); acc.y = fmaf(v6, a6.y, acc.y);
            acc.z = fmaf(v6, a6.z, acc.z); acc.w = fmaf(v6, a6.w, acc.w);
            acc.x = fmaf(v7, a7.x, acc.x); acc.y = fmaf(v7, a7.y, acc.y);
            acc.z = fmaf(v7, a7.z, acc.z); acc.w = fmaf(v7, a7.w, acc.w);
        }
    }
    // 2-wide tail.
    for (; k + 2 <= cc; k += 2) {
        int4 p = __ldg(&bk4[k >> 1]);
        float4 a0 = __ldg(&A4[(size_t)p.x * 16 + sub]);
        float4 a1 = __ldg(&A4[(size_t)p.z * 16 + sub]);
        float v0 = __int_as_float(p.y), v1 = __int_as_float(p.w);
        acc.x = fmaf(v0, a0.x, acc.x); acc.y = fmaf(v0, a0.y, acc.y);
        acc.z = fmaf(v0, a0.z, acc.z); acc.w = fmaf(v0, a0.w, acc.w);
        acc.x = fmaf(v1, a1.x, acc.x); acc.y = fmaf(v1, a1.y, acc.y);
        acc.z = fmaf(v1, a1.z, acc.z); acc.w = fmaf(v1, a1.w, acc.w);
    }
    // Scalar tail (0-1 entries).
    if (k < cc) {
        int2 e = __ldg(&((const int2*)bk4)[k]);
        float v  = __int_as_float(e.y);
        float4 a = __ldg(&A4[(size_t)e.x * 16 + sub]);
        acc.x = fmaf(v, a.x, acc.x); acc.y = fmaf(v, a.y, acc.y);
        acc.z = fmaf(v, a.z, acc.z); acc.w = fmaf(v, a.w, acc.w);
    }

    // Spill entries (unreachable for this dataset: max row degree ~40 << 64;
    // kept for correctness).
    if (c > BUCKET_CAP) {
        int n = d_ovf_cnt;
        if (n > OVF_CAP) n = OVF_CAP;
        for (int j = 0; j < n; j++) {
            int i = d_ovf[j];
            if (rows[i] == row) {
                float v  = vals[i];
                float4 a = __ldg(&A4[(size_t)cols[i] * 16 + sub]);
                acc.x = fmaf(v, a.x, acc.x); acc.y = fmaf(v, a.y, acc.y);
                acc.z = fmaf(v, a.z, acc.z); acc.w = fmaf(v, a.w, acc.w);
            }
        }
    }

    if (row < m) {
        out4[(size_t)row * 16 + sub] = acc;      // warp-wide 512B store
        if (sub == 0) d_cnt[row] = 0;            // reset for next call
    }
    if (gtid == 0) d_ovf_cnt = 0;
}

extern "C" void kernel_launch(void* const* d_in, const int* in_sizes, int n_in,
                              void* d_out, int out_size) {
    const float* vals = (const float*)d_in[0];
    const float* A    = (const float*)d_in[1];
    const int*   rows = (const int*)d_in[2];
    const int*   cols = (const int*)d_in[3];
    float*       out  = (float*)d_out;

    int nnz = in_sizes[0];
    int m   = out_size / N_COLS;
    if (m > M_ROWS) m = M_ROWS;   // scratch capacity bound (shapes are fixed)

    // Phase B: bin into buckets (4 nnz per thread)
    {
        int threads = 256;
        int quads   = (nnz + 3) / 4;
        int blocks  = (quads + threads - 1) / threads;
        phaseB_scatter<<<blocks, threads>>>((const float4*)vals,
                                            (const int4*)rows,
                                            (const int4*)cols, nnz);
    }
    // Phase C: half-warp-per-row gather SpMM (2 rows per warp, pipelined)
    {
        int threads   = 256;                     // 8 warps = 16 rows / block
        int row_pairs = (m + 1) / 2;
        int blocks    = (row_pairs * 32 + threads - 1) / threads;
        phaseC_spmm<<<blocks, threads>>>((const float4*)A, (float4*)out,
                                         vals, rows, cols, m);
    }
}